// round 1
// baseline (speedup 1.0000x reference)
#include <cuda_runtime.h>
#include <math.h>

// Shapes (fixed by the problem)
#define LL   1024
#define BSZ  4
#define DD   1024
#define NHH  16
#define DHH  64
#define PD   2048          // 2*D
#define RR   4096          // L*BS
#define NB   64            // BS*NH batch count for attention

// Scratch (device globals: allocation-free kernel_launch)
__device__ float g_proj[(size_t)RR * PD];            // 32 MB  : x@Wi^T + bi, rows r=l*4+b
__device__ float g_hid [(size_t)NHH * RR * LL];      // 268 MB : hid[k][r][h]
__device__ float g_logits[(size_t)NB * LL * LL];     // 268 MB : logits/probs[i][l][m]
__device__ float g_outcat[(size_t)RR * DD];          // 17 MB  : concat attention out, rows r=l*4+b

// ---------------------------------------------------------------------------
// Generic 128x128x16 tiled GEMM, C = A * B^T + bias   (A: MxK rowmaj, B: NxK rowmaj)
// ---------------------------------------------------------------------------
__global__ void __launch_bounds__(256) gemm_nt_bias(
    const float* __restrict__ A, int lda,
    const float* __restrict__ B, int ldb,
    const float* __restrict__ bias,
    float* __restrict__ C, int ldc,
    int K)
{
    __shared__ __align__(16) float As[16][128];
    __shared__ __align__(16) float Bs[16][128];
    const int bm  = blockIdx.y * 128;
    const int bn  = blockIdx.x * 128;
    const int tid = threadIdx.x;
    const int lr  = tid >> 2;
    const int lc4 = (tid & 3) * 4;
    const int ty  = tid >> 4, tx = tid & 15;

    float acc[8][8] = {};

    for (int k0 = 0; k0 < K; k0 += 16) {
#pragma unroll
        for (int rr = 0; rr < 2; rr++) {
            int r = lr + rr * 64;
            float4 a = *(const float4*)&A[(size_t)(bm + r) * lda + k0 + lc4];
            As[lc4+0][r] = a.x; As[lc4+1][r] = a.y; As[lc4+2][r] = a.z; As[lc4+3][r] = a.w;
            float4 b = *(const float4*)&B[(size_t)(bn + r) * ldb + k0 + lc4];
            Bs[lc4+0][r] = b.x; Bs[lc4+1][r] = b.y; Bs[lc4+2][r] = b.z; Bs[lc4+3][r] = b.w;
        }
        __syncthreads();
#pragma unroll
        for (int kk = 0; kk < 16; kk++) {
            float ra[8], rb[8];
#pragma unroll
            for (int i = 0; i < 8; i++) ra[i] = As[kk][ty*8+i];
#pragma unroll
            for (int j = 0; j < 8; j++) rb[j] = Bs[kk][tx*8+j];
#pragma unroll
            for (int i = 0; i < 8; i++)
#pragma unroll
                for (int j = 0; j < 8; j++)
                    acc[i][j] = fmaf(ra[i], rb[j], acc[i][j]);
        }
        __syncthreads();
    }
#pragma unroll
    for (int i = 0; i < 8; i++) {
        int m = bm + ty*8 + i;
#pragma unroll
        for (int j = 0; j < 8; j++) {
            int n = bn + tx*8 + j;
            C[(size_t)m * ldc + n] = acc[i][j] + bias[n];
        }
    }
}

// ---------------------------------------------------------------------------
// Kernel 2: hid[k][r][h] = relu( proj[r, k*64 : k*64+64] @ w1[k] + b1[k] )
// A: 4096x64 (lda=2048), B: 64x1024 NN, per-head via blockIdx.z
// ---------------------------------------------------------------------------
__global__ void __launch_bounds__(256) gemm_hid(
    const float* __restrict__ w1, const float* __restrict__ b1)
{
    const int head = blockIdx.z;
    const float* A    = g_proj + head * DHH;                 // lda = PD
    const float* B    = w1 + (size_t)head * DHH * LL;        // 64 x 1024, NN
    const float* bias = b1 + head * LL;
    float* C          = g_hid + (size_t)head * RR * LL;

    __shared__ __align__(16) float As[16][128];
    __shared__ __align__(16) float Bs[16][128];
    const int bm  = blockIdx.y * 128;
    const int bn  = blockIdx.x * 128;
    const int tid = threadIdx.x;
    const int lr  = tid >> 2;
    const int lc4 = (tid & 3) * 4;
    const int br  = tid >> 4;
    const int bc4 = (tid & 15) * 4;
    const int ty  = tid >> 4, tx = tid & 15;

    float acc[8][8] = {};

    for (int k0 = 0; k0 < DHH; k0 += 16) {
#pragma unroll
        for (int rr = 0; rr < 2; rr++) {
            int r = lr + rr * 64;
            float4 a = *(const float4*)&A[(size_t)(bm + r) * PD + k0 + lc4];
            As[lc4+0][r] = a.x; As[lc4+1][r] = a.y; As[lc4+2][r] = a.z; As[lc4+3][r] = a.w;
        }
        {
            float4 b0 = *(const float4*)&B[(size_t)(k0 + br) * LL + bn + bc4];
            float4 b1v = *(const float4*)&B[(size_t)(k0 + br) * LL + bn + bc4 + 64];
            *(float4*)&Bs[br][bc4]      = b0;
            *(float4*)&Bs[br][bc4 + 64] = b1v;
        }
        __syncthreads();
#pragma unroll
        for (int kk = 0; kk < 16; kk++) {
            float ra[8], rb[8];
#pragma unroll
            for (int i = 0; i < 8; i++) ra[i] = As[kk][ty*8+i];
#pragma unroll
            for (int j = 0; j < 8; j++) rb[j] = Bs[kk][tx*8+j];
#pragma unroll
            for (int i = 0; i < 8; i++)
#pragma unroll
                for (int j = 0; j < 8; j++)
                    acc[i][j] = fmaf(ra[i], rb[j], acc[i][j]);
        }
        __syncthreads();
    }
#pragma unroll
    for (int i = 0; i < 8; i++) {
        int m = bm + ty*8 + i;
#pragma unroll
        for (int j = 0; j < 8; j++) {
            int n = bn + tx*8 + j;
            C[(size_t)m * LL + n] = fmaxf(acc[i][j] + bias[n], 0.0f);
        }
    }
}

// ---------------------------------------------------------------------------
// Kernel 3: logits[i][l][m] = hid[kq][l*4+bq][:] @ w2[kq][:, m] + b2[kq][m]
// i = kq*4 + bq.  Lower-triangular tiles only (tj <= ti) — causal mask.
// ---------------------------------------------------------------------------
__global__ void __launch_bounds__(256) gemm_logits(
    const float* __restrict__ w2, const float* __restrict__ b2)
{
    const int ti = blockIdx.y, tj = blockIdx.x;
    if (tj > ti) return;                                     // skipped by causality
    const int i  = blockIdx.z;
    const int kq = i >> 2, bq = i & 3;
    const float* Ah   = g_hid + (size_t)kq * RR * LL;        // row l -> (l*4+bq)*1024
    const float* B    = w2 + (size_t)kq * LL * LL;           // 1024x1024 NN
    const float* bias = b2 + kq * LL;
    float* C          = g_logits + (size_t)i * LL * LL;

    __shared__ __align__(16) float As[16][128];
    __shared__ __align__(16) float Bs[16][128];
    const int bm  = ti * 128;
    const int bn  = tj * 128;
    const int tid = threadIdx.x;
    const int lr  = tid >> 2;
    const int lc4 = (tid & 3) * 4;
    const int br  = tid >> 4;
    const int bc4 = (tid & 15) * 4;
    const int ty  = tid >> 4, tx = tid & 15;

    float acc[8][8] = {};

    for (int k0 = 0; k0 < LL; k0 += 16) {
#pragma unroll
        for (int rr = 0; rr < 2; rr++) {
            int r = lr + rr * 64;
            float4 a = *(const float4*)&Ah[((size_t)(bm + r) * 4 + bq) * LL + k0 + lc4];
            As[lc4+0][r] = a.x; As[lc4+1][r] = a.y; As[lc4+2][r] = a.z; As[lc4+3][r] = a.w;
        }
        {
            float4 b0 = *(const float4*)&B[(size_t)(k0 + br) * LL + bn + bc4];
            float4 b1v = *(const float4*)&B[(size_t)(k0 + br) * LL + bn + bc4 + 64];
            *(float4*)&Bs[br][bc4]      = b0;
            *(float4*)&Bs[br][bc4 + 64] = b1v;
        }
        __syncthreads();
#pragma unroll
        for (int kk = 0; kk < 16; kk++) {
            float ra[8], rb[8];
#pragma unroll
            for (int ii = 0; ii < 8; ii++) ra[ii] = As[kk][ty*8+ii];
#pragma unroll
            for (int jj = 0; jj < 8; jj++) rb[jj] = Bs[kk][tx*8+jj];
#pragma unroll
            for (int ii = 0; ii < 8; ii++)
#pragma unroll
                for (int jj = 0; jj < 8; jj++)
                    acc[ii][jj] = fmaf(ra[ii], rb[jj], acc[ii][jj]);
        }
        __syncthreads();
    }
#pragma unroll
    for (int ii = 0; ii < 8; ii++) {
        int m = bm + ty*8 + ii;
#pragma unroll
        for (int jj = 0; jj < 8; jj++) {
            int n = bn + tx*8 + jj;
            C[(size_t)m * LL + n] = acc[ii][jj] + bias[n];
        }
    }
}

// ---------------------------------------------------------------------------
// Kernel 4: causal softmax over m in [0, l]; zero-fill (l, diag tile end)
// so the PV GEMM can read whole 128-aligned K panels.
// ---------------------------------------------------------------------------
__global__ void __launch_bounds__(256) softmax_causal()
{
    const int l = blockIdx.x;
    const int i = blockIdx.y;
    float* row = g_logits + ((size_t)i * LL + l) * LL;
    const int n = l + 1;
    const int diagEnd = ((l >> 7) + 1) << 7;

    __shared__ float buf[LL];
    __shared__ float red[256];
    const int t = threadIdx.x;

    float vmax = -1e30f;
    for (int m = t; m < n; m += 256) { float v = row[m]; buf[m] = v; vmax = fmaxf(vmax, v); }
    red[t] = vmax;
    __syncthreads();
    for (int s = 128; s > 0; s >>= 1) { if (t < s) red[t] = fmaxf(red[t], red[t + s]); __syncthreads(); }
    vmax = red[0];
    __syncthreads();

    float ssum = 0.0f;
    for (int m = t; m < n; m += 256) { float e = __expf(buf[m] - vmax); buf[m] = e; ssum += e; }
    red[t] = ssum;
    __syncthreads();
    for (int s = 128; s > 0; s >>= 1) { if (t < s) red[t] += red[t + s]; __syncthreads(); }
    const float inv = 1.0f / red[0];

    for (int m = t; m < n; m += 256) row[m] = buf[m] * inv;
    for (int m = n + t; m < diagEnd; m += 256) row[m] = 0.0f;
}

// ---------------------------------------------------------------------------
// Kernel 5: out[i] = probs[i] @ v[i];  v[i][m][d] = proj[m*4+bv][1024 + kv*64 + d]
// with bv = i/16, kv = i%16 (reference's mismatched batch pairing).
// Writes directly into concat layout: outcat[(l*4+bv)*1024 + kv*64 + d].
// K-loop only over computed/zero-filled panels: [0, (rowtile+1)*128).
// ---------------------------------------------------------------------------
__global__ void __launch_bounds__(256) gemm_pv()
{
    const int i  = blockIdx.y;
    const int bt = blockIdx.x;            // 128-row tile
    const int bv = i >> 4, kv = i & 15;
    const float* P = g_logits + (size_t)i * LL * LL;
    const float* V = g_proj + (size_t)bv * PD + DD + kv * DHH;   // stride 8192 per m

    __shared__ __align__(16) float Ps[16][128];
    __shared__ __align__(16) float Vs[16][64];
    const int tid = threadIdx.x;
    const int lr  = tid >> 2;
    const int lc4 = (tid & 3) * 4;
    const int vr  = tid >> 4;
    const int vc4 = (tid & 15) * 4;
    const int ty  = tid >> 4, tx = tid & 15;   // 8 rows x 4 cols per thread
    const int bm  = bt * 128;
    const int kEnd = bm + 128;

    float acc[8][4] = {};

    for (int k0 = 0; k0 < kEnd; k0 += 16) {
#pragma unroll
        for (int rr = 0; rr < 2; rr++) {
            int r = lr + rr * 64;
            float4 a = *(const float4*)&P[(size_t)(bm + r) * LL + k0 + lc4];
            Ps[lc4+0][r] = a.x; Ps[lc4+1][r] = a.y; Ps[lc4+2][r] = a.z; Ps[lc4+3][r] = a.w;
        }
        {
            float4 b = *(const float4*)&V[(size_t)(k0 + vr) * (size_t)(BSZ * PD) + vc4];
            *(float4*)&Vs[vr][vc4] = b;
        }
        __syncthreads();
#pragma unroll
        for (int kk = 0; kk < 16; kk++) {
            float ra[8], rb[4];
#pragma unroll
            for (int ii = 0; ii < 8; ii++) ra[ii] = Ps[kk][ty*8+ii];
#pragma unroll
            for (int jj = 0; jj < 4; jj++) rb[jj] = Vs[kk][tx*4+jj];
#pragma unroll
            for (int ii = 0; ii < 8; ii++)
#pragma unroll
                for (int jj = 0; jj < 4; jj++)
                    acc[ii][jj] = fmaf(ra[ii], rb[jj], acc[ii][jj]);
        }
        __syncthreads();
    }
#pragma unroll
    for (int ii = 0; ii < 8; ii++) {
        int l = bm + ty*8 + ii;
        float* dst = g_outcat + ((size_t)l * 4 + bv) * DD + kv * DHH + tx * 4;
#pragma unroll
        for (int jj = 0; jj < 4; jj++) dst[jj] = acc[ii][jj];
    }
}

// ---------------------------------------------------------------------------
extern "C" void kernel_launch(void* const* d_in, const int* in_sizes, int n_in,
                              void* d_out, int out_size)
{
    (void)in_sizes; (void)n_in; (void)out_size;
    const float* x  = (const float*)d_in[0];
    // d_in[1] = attention_mask: exactly causal -1e9 mask; implemented structurally.
    const float* Wi = (const float*)d_in[2];
    const float* bi = (const float*)d_in[3];
    const float* w1 = (const float*)d_in[4];
    const float* b1 = (const float*)d_in[5];
    const float* w2 = (const float*)d_in[6];
    const float* b2 = (const float*)d_in[7];
    const float* Wo = (const float*)d_in[8];
    const float* bo = (const float*)d_in[9];
    float* out = (float*)d_out;

    float *proj, *outcat;
    cudaGetSymbolAddress((void**)&proj,   g_proj);
    cudaGetSymbolAddress((void**)&outcat, g_outcat);

    // K1: proj = x @ Wi^T + bi                     (M=4096, N=2048, K=1024)
    gemm_nt_bias<<<dim3(PD/128, RR/128), 256>>>(x, DD, Wi, DD, bi, proj, PD, DD);
    // K2: hid = relu(q @ w1 + b1), per head        (16 x [4096 x 1024 x 64])
    gemm_hid<<<dim3(LL/128, RR/128, NHH), 256>>>(w1, b1);
    // K3: logits (lower-tri tiles only) + b2       (64 x tri[1024 x 1024 x 1024])
    gemm_logits<<<dim3(LL/128, LL/128, NB), 256>>>(w2, b2);
    // K4: causal softmax in place (+ zero-fill to diag tile boundary)
    softmax_causal<<<dim3(LL, NB), 256>>>();
    // K5: out = probs @ v  -> concat layout        (64 x [1024 x 64 x <=1024])
    gemm_pv<<<dim3(LL/128, NB), 256>>>();
    // K6: y = outcat @ Wo^T + bo                   (M=4096, N=1024, K=1024)
    gemm_nt_bias<<<dim3(DD/128, RR/128), 256>>>(outcat, DD, Wo, DD, bo, out, DD, DD);
}

// round 3
// speedup vs baseline: 2.0153x; 2.0153x over previous
#include <cuda_runtime.h>
#include <cstdint>
#include <math.h>

// Shapes (fixed by the problem)
#define LL   1024
#define BSZ  4
#define DD   1024
#define NHH  16
#define DHH  64
#define PD   2048          // 2*D
#define RR   4096          // L*BS
#define NB   64            // BS*NH batch count for attention

// Scratch (device globals: allocation-free kernel_launch)
__device__ float g_proj[(size_t)RR * PD];            // 32 MB
__device__ float g_hid [(size_t)NHH * RR * LL];      // 268 MB
__device__ float g_logits[(size_t)NB * LL * LL];     // 268 MB
__device__ float g_outcat[(size_t)RR * DD];          // 17 MB
__device__ float g_w1t[(size_t)NHH * LL * DHH];      // 4 MB : w1 -> [h][H][DH] K-major
__device__ float g_w2t[(size_t)NHH * LL * LL];       // 64 MB: w2 -> [h][L][H]  K-major

// ---------------------------------------------------------------------------
__device__ __forceinline__ uint32_t f2tf32(float f) {
    uint32_t u;
    asm("cvt.rna.tf32.f32 %0, %1;" : "=r"(u) : "f"(f));
    return u;
}

__device__ __forceinline__ void mma_tf32(float c[4], const uint32_t a[4], const uint32_t b[2]) {
    asm volatile(
        "mma.sync.aligned.m16n8k8.row.col.f32.tf32.tf32.f32 "
        "{%0,%1,%2,%3}, {%4,%5,%6,%7}, {%8,%9}, {%0,%1,%2,%3};"
        : "+f"(c[0]), "+f"(c[1]), "+f"(c[2]), "+f"(c[3])
        : "r"(a[0]), "r"(a[1]), "r"(a[2]), "r"(a[3]), "r"(b[0]), "r"(b[1]));
}

// ---------------------------------------------------------------------------
// Tensor-core tf32 GEMM: C = act(A @ B^T + bias).
// A rows K-major (stride sA), B rows K-major (stride sB).
// Block tile 128x128, K-chunk 16, 8 warps (4 M x 2 N), warp tile 32x64.
// SMEM rows padded to 20 floats -> conflict-free fragment LDS.
// mode: 0=proj  1=hid(relu)  2=logits(tri)  3=out
// ---------------------------------------------------------------------------
#define PADK 20

__global__ void __launch_bounds__(256, 2) gemm_mma(
    int mode, int K, int relu,
    const float* __restrict__ Ain, const float* __restrict__ Bin,
    const float* __restrict__ biasIn, float* __restrict__ Cout)
{
    const int bm = blockIdx.y * 128;
    const int bn = blockIdx.x * 128;

    const float* A; const float* B; const float* bias; float* C;
    size_t sA, sB, ldc;
    if (mode == 0) {            // proj = x @ Wi^T + bi
        A = Ain; sA = DD; B = Bin; sB = DD; bias = biasIn; C = Cout; ldc = PD;
    } else if (mode == 1) {     // hid[h] = relu(proj[:, h*64:] @ w1t[h]^T + b1[h])
        int h = blockIdx.z;
        A = Ain + h * DHH;                sA = PD;
        B = Bin + (size_t)h * LL * DHH;   sB = DHH;
        bias = biasIn + h * LL;
        C = Cout + (size_t)h * RR * LL;   ldc = LL;
    } else if (mode == 2) {     // logits[i] = hid_rows(bq) @ w2t[kq]^T + b2[kq]
        if (blockIdx.x > blockIdx.y) return;    // causal: lower-tri tiles only
        int i = blockIdx.z, kq = i >> 2, bq = i & 3;
        A = Ain + (size_t)kq * RR * LL + bq * LL; sA = 4 * LL;
        B = Bin + (size_t)kq * LL * LL;           sB = LL;
        bias = biasIn + kq * LL;
        C = Cout + (size_t)i * LL * LL;           ldc = LL;
    } else {                    // out = outcat @ Wo^T + bo
        A = Ain; sA = DD; B = Bin; sB = DD; bias = biasIn; C = Cout; ldc = DD;
    }

    __shared__ __align__(16) float As[2][128][PADK];
    __shared__ __align__(16) float Bs[2][128][PADK];

    const int tid   = threadIdx.x;
    const int wid   = tid >> 5, lane = tid & 31;
    const int warpM = wid & 3;          // 4 warps along M (32 rows each)
    const int warpN = wid >> 2;         // 2 warps along N (64 cols each)
    const int grp   = lane >> 2;        // 0..7
    const int quad  = lane & 3;         // 0..3

    // gmem staging: each thread owns 2 float4 of A and 2 of B per chunk
    const int f0 = tid * 2;
    const int r0 = f0 >> 2,       c0 = (f0 & 3) * 4;
    const int r1 = (f0 + 1) >> 2, c1 = ((f0 + 1) & 3) * 4;

    float acc[2][8][4] = {};
    float4 stA0, stA1, stB0, stB1;

    const int T = K / 16;

    // prologue: chunk 0
    stA0 = *(const float4*)&A[(size_t)(bm + r0) * sA + c0];
    stA1 = *(const float4*)&A[(size_t)(bm + r1) * sA + c1];
    stB0 = *(const float4*)&B[(size_t)(bn + r0) * sB + c0];
    stB1 = *(const float4*)&B[(size_t)(bn + r1) * sB + c1];
    {
        uint4 ua0 = make_uint4(f2tf32(stA0.x), f2tf32(stA0.y), f2tf32(stA0.z), f2tf32(stA0.w));
        uint4 ua1 = make_uint4(f2tf32(stA1.x), f2tf32(stA1.y), f2tf32(stA1.z), f2tf32(stA1.w));
        uint4 ub0 = make_uint4(f2tf32(stB0.x), f2tf32(stB0.y), f2tf32(stB0.z), f2tf32(stB0.w));
        uint4 ub1 = make_uint4(f2tf32(stB1.x), f2tf32(stB1.y), f2tf32(stB1.z), f2tf32(stB1.w));
        *(uint4*)&As[0][r0][c0] = ua0; *(uint4*)&As[0][r1][c1] = ua1;
        *(uint4*)&Bs[0][r0][c0] = ub0; *(uint4*)&Bs[0][r1][c1] = ub1;
    }
    __syncthreads();

#pragma unroll 1
    for (int t = 0; t < T; t++) {
        const int buf = t & 1;
        const bool more = (t + 1) < T;

        if (more) {
            const int k0 = (t + 1) * 16;
            stA0 = *(const float4*)&A[(size_t)(bm + r0) * sA + k0 + c0];
            stA1 = *(const float4*)&A[(size_t)(bm + r1) * sA + k0 + c1];
            stB0 = *(const float4*)&B[(size_t)(bn + r0) * sB + k0 + c0];
            stB1 = *(const float4*)&B[(size_t)(bn + r1) * sB + k0 + c1];
        }

        // compute chunk t: 2 k-steps of 8
#pragma unroll
        for (int ks = 0; ks < 2; ks++) {
            const int k = ks * 8 + quad;
            uint32_t af[2][4], bf[8][2];
#pragma unroll
            for (int mt = 0; mt < 2; mt++) {
                const int m = warpM * 32 + mt * 16 + grp;
                af[mt][0] = __float_as_uint(As[buf][m    ][k    ]);
                af[mt][1] = __float_as_uint(As[buf][m + 8][k    ]);
                af[mt][2] = __float_as_uint(As[buf][m    ][k + 4]);
                af[mt][3] = __float_as_uint(As[buf][m + 8][k + 4]);
            }
#pragma unroll
            for (int nt = 0; nt < 8; nt++) {
                const int n = warpN * 64 + nt * 8 + grp;
                bf[nt][0] = __float_as_uint(Bs[buf][n][k    ]);
                bf[nt][1] = __float_as_uint(Bs[buf][n][k + 4]);
            }
#pragma unroll
            for (int mt = 0; mt < 2; mt++)
#pragma unroll
                for (int nt = 0; nt < 8; nt++)
                    mma_tf32(acc[mt][nt], af[mt], bf[nt]);
        }

        if (more) {
            const int nb = (t + 1) & 1;
            uint4 ua0 = make_uint4(f2tf32(stA0.x), f2tf32(stA0.y), f2tf32(stA0.z), f2tf32(stA0.w));
            uint4 ua1 = make_uint4(f2tf32(stA1.x), f2tf32(stA1.y), f2tf32(stA1.z), f2tf32(stA1.w));
            uint4 ub0 = make_uint4(f2tf32(stB0.x), f2tf32(stB0.y), f2tf32(stB0.z), f2tf32(stB0.w));
            uint4 ub1 = make_uint4(f2tf32(stB1.x), f2tf32(stB1.y), f2tf32(stB1.z), f2tf32(stB1.w));
            *(uint4*)&As[nb][r0][c0] = ua0; *(uint4*)&As[nb][r1][c1] = ua1;
            *(uint4*)&Bs[nb][r0][c0] = ub0; *(uint4*)&Bs[nb][r1][c1] = ub1;
        }
        __syncthreads();
    }

    // epilogue: c frag mapping m16n8: (row=grp, col=quad*2), (row+8, col..col+1)
#pragma unroll
    for (int mt = 0; mt < 2; mt++) {
        const int m = bm + warpM * 32 + mt * 16 + grp;
#pragma unroll
        for (int nt = 0; nt < 8; nt++) {
            const int n = bn + warpN * 64 + nt * 8 + quad * 2;
            float b0 = bias[n], b1 = bias[n + 1];
            float2 v0 = make_float2(acc[mt][nt][0] + b0, acc[mt][nt][1] + b1);
            float2 v1 = make_float2(acc[mt][nt][2] + b0, acc[mt][nt][3] + b1);
            if (relu) {
                v0.x = fmaxf(v0.x, 0.f); v0.y = fmaxf(v0.y, 0.f);
                v1.x = fmaxf(v1.x, 0.f); v1.y = fmaxf(v1.y, 0.f);
            }
            *(float2*)&C[(size_t)m * ldc + n]       = v0;
            *(float2*)&C[(size_t)(m + 8) * ldc + n] = v1;
        }
    }
}

// ---------------------------------------------------------------------------
// Tiled transpose: src [z][R][C] -> dst [z][C][R]
// ---------------------------------------------------------------------------
__global__ void transpose_rk(const float* __restrict__ src, float* __restrict__ dst,
                             int R, int C)
{
    __shared__ float t[32][33];
    const size_t zo = (size_t)blockIdx.z * R * C;
    const int c0 = blockIdx.x * 32, r0 = blockIdx.y * 32;
    const int tx = threadIdx.x, ty = threadIdx.y;
#pragma unroll
    for (int j = 0; j < 32; j += 8)
        t[ty + j][tx] = src[zo + (size_t)(r0 + ty + j) * C + c0 + tx];
    __syncthreads();
#pragma unroll
    for (int j = 0; j < 32; j += 8)
        dst[zo + (size_t)(c0 + ty + j) * R + r0 + tx] = t[tx][ty + j];
}

// ---------------------------------------------------------------------------
// Causal softmax over m in [0, l]; zero-fill (l, diag tile end) for PV GEMM.
// ---------------------------------------------------------------------------
__global__ void __launch_bounds__(256) softmax_causal()
{
    const int l = blockIdx.x;
    const int i = blockIdx.y;
    float* row = g_logits + ((size_t)i * LL + l) * LL;
    const int n = l + 1;
    const int diagEnd = ((l >> 7) + 1) << 7;

    __shared__ float buf[LL];
    __shared__ float red[256];
    const int t = threadIdx.x;

    float vmax = -1e30f;
    for (int m = t; m < n; m += 256) { float v = row[m]; buf[m] = v; vmax = fmaxf(vmax, v); }
    red[t] = vmax;
    __syncthreads();
    for (int s = 128; s > 0; s >>= 1) { if (t < s) red[t] = fmaxf(red[t], red[t + s]); __syncthreads(); }
    vmax = red[0];
    __syncthreads();

    float ssum = 0.0f;
    for (int m = t; m < n; m += 256) { float e = __expf(buf[m] - vmax); buf[m] = e; ssum += e; }
    red[t] = ssum;
    __syncthreads();
    for (int s = 128; s > 0; s >>= 1) { if (t < s) red[t] += red[t + s]; __syncthreads(); }
    const float inv = 1.0f / red[0];

    for (int m = t; m < n; m += 256) row[m] = buf[m] * inv;
    for (int m = n + t; m < diagEnd; m += 256) row[m] = 0.0f;
}

// ---------------------------------------------------------------------------
// PV: out[i] = probs[i] @ v[i] -> concat layout (SIMT; memory-bound)
// v[i][m][d] = proj[m*4+bv][1024 + kv*64 + d], bv = i/16, kv = i%16.
// ---------------------------------------------------------------------------
__global__ void __launch_bounds__(256) gemm_pv()
{
    const int i  = blockIdx.y;
    const int bt = blockIdx.x;
    const int bv = i >> 4, kv = i & 15;
    const float* P = g_logits + (size_t)i * LL * LL;
    const float* V = g_proj + (size_t)bv * PD + DD + kv * DHH;

    __shared__ __align__(16) float Ps[16][128];
    __shared__ __align__(16) float Vs[16][64];
    const int tid = threadIdx.x;
    const int lr  = tid >> 2;
    const int lc4 = (tid & 3) * 4;
    const int vr  = tid >> 4;
    const int vc4 = (tid & 15) * 4;
    const int ty  = tid >> 4, tx = tid & 15;
    const int bm  = bt * 128;
    const int kEnd = bm + 128;

    float acc[8][4] = {};

    for (int k0 = 0; k0 < kEnd; k0 += 16) {
#pragma unroll
        for (int rr = 0; rr < 2; rr++) {
            int r = lr + rr * 64;
            float4 a = *(const float4*)&P[(size_t)(bm + r) * LL + k0 + lc4];
            Ps[lc4+0][r] = a.x; Ps[lc4+1][r] = a.y; Ps[lc4+2][r] = a.z; Ps[lc4+3][r] = a.w;
        }
        {
            float4 b = *(const float4*)&V[(size_t)(k0 + vr) * (size_t)(BSZ * PD) + vc4];
            *(float4*)&Vs[vr][vc4] = b;
        }
        __syncthreads();
#pragma unroll
        for (int kk = 0; kk < 16; kk++) {
            float ra[8], rb[4];
#pragma unroll
            for (int ii = 0; ii < 8; ii++) ra[ii] = Ps[kk][ty*8+ii];
#pragma unroll
            for (int jj = 0; jj < 4; jj++) rb[jj] = Vs[kk][tx*4+jj];
#pragma unroll
            for (int ii = 0; ii < 8; ii++)
#pragma unroll
                for (int jj = 0; jj < 4; jj++)
                    acc[ii][jj] = fmaf(ra[ii], rb[jj], acc[ii][jj]);
        }
        __syncthreads();
    }
#pragma unroll
    for (int ii = 0; ii < 8; ii++) {
        int l = bm + ty*8 + ii;
        float* dst = g_outcat + ((size_t)l * 4 + bv) * DD + kv * DHH + tx * 4;
#pragma unroll
        for (int jj = 0; jj < 4; jj++) dst[jj] = acc[ii][jj];
    }
}

// ---------------------------------------------------------------------------
extern "C" void kernel_launch(void* const* d_in, const int* in_sizes, int n_in,
                              void* d_out, int out_size)
{
    (void)in_sizes; (void)n_in; (void)out_size;
    const float* x  = (const float*)d_in[0];
    // d_in[1] = attention_mask (exactly causal; implemented structurally)
    const float* Wi = (const float*)d_in[2];
    const float* bi = (const float*)d_in[3];
    const float* w1 = (const float*)d_in[4];
    const float* b1 = (const float*)d_in[5];
    const float* w2 = (const float*)d_in[6];
    const float* b2 = (const float*)d_in[7];
    const float* Wo = (const float*)d_in[8];
    const float* bo = (const float*)d_in[9];
    float* out = (float*)d_out;

    float *proj, *hid, *logits, *outcat, *w1t, *w2t;
    cudaGetSymbolAddress((void**)&proj,   g_proj);
    cudaGetSymbolAddress((void**)&hid,    g_hid);
    cudaGetSymbolAddress((void**)&logits, g_logits);
    cudaGetSymbolAddress((void**)&outcat, g_outcat);
    cudaGetSymbolAddress((void**)&w1t,    g_w1t);
    cudaGetSymbolAddress((void**)&w2t,    g_w2t);

    // weight transposes to K-major (w1: [h][64][1024] -> [h][1024][64]; w2 likewise)
    transpose_rk<<<dim3(32, 2, NHH),  dim3(32, 8)>>>(w1, w1t, DHH, LL);
    transpose_rk<<<dim3(32, 32, NHH), dim3(32, 8)>>>(w2, w2t, LL, LL);

    // K1: proj = x @ Wi^T + bi                 (4096 x 2048 x 1024)
    gemm_mma<<<dim3(PD/128, RR/128), 256>>>(0, DD, 0, x, Wi, bi, proj);
    // K2: hid = relu(q @ w1 + b1)              (16 x [4096 x 1024 x 64])
    gemm_mma<<<dim3(LL/128, RR/128, NHH), 256>>>(1, DHH, 1, proj, w1t, b1, hid);
    // K3: logits (lower-tri tiles) + b2        (64 x tri[1024 x 1024 x 1024])
    gemm_mma<<<dim3(LL/128, LL/128, NB), 256>>>(2, LL, 0, hid, w2t, b2, logits);
    // K4: causal softmax in place
    softmax_causal<<<dim3(LL, NB), 256>>>();
    // K5: out = probs @ v -> concat layout
    gemm_pv<<<dim3(LL/128, NB), 256>>>();
    // K6: y = outcat @ Wo^T + bo               (4096 x 1024 x 1024)
    gemm_mma<<<dim3(DD/128, RR/128), 256>>>(3, DD, 0, outcat, Wo, bo, out);
}

// round 4
// speedup vs baseline: 2.7302x; 1.3547x over previous
#include <cuda_runtime.h>
#include <cstdint>
#include <math.h>

// Shapes (fixed by the problem)
#define LL   1024
#define BSZ  4
#define DD   1024
#define NHH  16
#define DHH  64
#define PD   2048          // 2*D
#define RR   4096          // L*BS
#define NB   64            // BS*NH batch count for attention

// Scratch (device globals: allocation-free kernel_launch)
__device__ float g_proj[(size_t)RR * PD];            // 32 MB
__device__ float g_hid [(size_t)NHH * RR * LL];      // 268 MB
__device__ float g_logits[(size_t)NB * LL * LL];     // 268 MB
__device__ float g_outcat[(size_t)RR * DD];          // 17 MB
__device__ float g_w1t[(size_t)NHH * LL * DHH];      // 4 MB : w1 -> [h][H][DH] K-major
__device__ float g_w2t[(size_t)NHH * LL * LL];       // 64 MB: w2 -> [h][L][H]  K-major

// ---------------------------------------------------------------------------
__device__ __forceinline__ uint32_t f2tf32(float f) {
    uint32_t u;
    asm("cvt.rna.tf32.f32 %0, %1;" : "=r"(u) : "f"(f));
    return u;
}
__device__ __forceinline__ uint32_t smem_u32(const void* p) {
    uint32_t a;
    asm("{ .reg .u64 t; cvta.to.shared.u64 t, %1; cvt.u32.u64 %0, t; }" : "=r"(a) : "l"(p));
    return a;
}
__device__ __forceinline__ void cp_async16(uint32_t dst, const void* src) {
    asm volatile("cp.async.cg.shared.global [%0], [%1], 16;" :: "r"(dst), "l"(src));
}
__device__ __forceinline__ void cp_commit() {
    asm volatile("cp.async.commit_group;" ::: "memory");
}
__device__ __forceinline__ void cp_wait1() {
    asm volatile("cp.async.wait_group 1;" ::: "memory");
}

__device__ __forceinline__ void mma_tf32(float c[4], const uint32_t a[4], const uint32_t b[2]) {
    asm volatile(
        "mma.sync.aligned.m16n8k8.row.col.f32.tf32.tf32.f32 "
        "{%0,%1,%2,%3}, {%4,%5,%6,%7}, {%8,%9}, {%0,%1,%2,%3};"
        : "+f"(c[0]), "+f"(c[1]), "+f"(c[2]), "+f"(c[3])
        : "r"(a[0]), "r"(a[1]), "r"(a[2]), "r"(a[3]), "r"(b[0]), "r"(b[1]));
}

// ---------------------------------------------------------------------------
// Tensor-core tf32 GEMM: C = act(A @ B^T + bias).
// Block tile 128x128, K-chunk 32, 3-stage cp.async pipeline, 8 warps (4Mx2N).
// smem holds raw f32 (canonical, PADK-padded rows); cvt.rna at fragment load.
// mode: 0=proj  1=hid(relu)  2=logits(tri)  3=out
// ---------------------------------------------------------------------------
#define PADK 36
#define STAGE_F (128 * PADK)             // floats per stage per matrix
#define SMEM_BYTES (2 * 3 * STAGE_F * 4) // 110592

__global__ void __launch_bounds__(256, 2) gemm_mma(
    int mode, int K, int relu,
    const float* __restrict__ Ain, const float* __restrict__ Bin,
    const float* __restrict__ biasIn, float* __restrict__ Cout)
{
    const int bm = blockIdx.y * 128;
    const int bn = blockIdx.x * 128;

    const float* A; const float* B; const float* bias; float* C;
    size_t sA, sB, ldc;
    if (mode == 0) {            // proj = x @ Wi^T + bi
        A = Ain; sA = DD; B = Bin; sB = DD; bias = biasIn; C = Cout; ldc = PD;
    } else if (mode == 1) {     // hid[h] = relu(proj[:, h*64:] @ w1t[h]^T + b1[h])
        int h = blockIdx.z;
        A = Ain + h * DHH;                sA = PD;
        B = Bin + (size_t)h * LL * DHH;   sB = DHH;
        bias = biasIn + h * LL;
        C = Cout + (size_t)h * RR * LL;   ldc = LL;
    } else if (mode == 2) {     // logits[i] = hid_rows(bq) @ w2t[kq]^T + b2[kq]
        if (blockIdx.x > blockIdx.y) return;    // causal: lower-tri tiles only
        int i = blockIdx.z, kq = i >> 2, bq = i & 3;
        A = Ain + (size_t)kq * RR * LL + bq * LL; sA = 4 * LL;
        B = Bin + (size_t)kq * LL * LL;           sB = LL;
        bias = biasIn + kq * LL;
        C = Cout + (size_t)i * LL * LL;           ldc = LL;
    } else {                    // out = outcat @ Wo^T + bo
        A = Ain; sA = DD; B = Bin; sB = DD; bias = biasIn; C = Cout; ldc = DD;
    }

    extern __shared__ __align__(16) float smem[];
    float* As = smem;                    // [3][128][PADK]
    float* Bs = smem + 3 * STAGE_F;      // [3][128][PADK]

    const int tid   = threadIdx.x;
    const int wid   = tid >> 5, lane = tid & 31;
    const int warpM = wid & 3;          // 4 warps along M (32 rows each)
    const int warpN = wid >> 2;         // 2 warps along N (64 cols each)
    const int grp   = lane >> 2;        // 0..7
    const int quad  = lane & 3;         // 0..3

    const int T = K / 32;

    // ---- stage issuer: 128 rows x 8 float4-cols per matrix, 8 cp.async/thread
    auto issue = [&](int chunk, int buf) {
        const int k0 = chunk * 32;
        float* sa = As + buf * STAGE_F;
        float* sb = Bs + buf * STAGE_F;
#pragma unroll
        for (int j = 0; j < 4; j++) {
            const int idx = tid + j * 256;          // 0..1023
            const int r = idx >> 3, c4 = (idx & 7) * 4;
            cp_async16(smem_u32(&sa[r * PADK + c4]),
                       &A[(size_t)(bm + r) * sA + k0 + c4]);
            cp_async16(smem_u32(&sb[r * PADK + c4]),
                       &B[(size_t)(bn + r) * sB + k0 + c4]);
        }
    };

    // prologue: stages 0,1
    issue(0, 0); cp_commit();
    if (1 < T) issue(1, 1);
    cp_commit();

    float acc[2][8][4] = {};

#pragma unroll 1
    for (int t = 0; t < T; t++) {
        cp_wait1();
        __syncthreads();

        if (t + 2 < T) issue(t + 2, (t + 2) % 3);
        cp_commit();

        const float* sa = As + (t % 3) * STAGE_F;
        const float* sb = Bs + (t % 3) * STAGE_F;

#pragma unroll
        for (int ks = 0; ks < 4; ks++) {
            const int k = ks * 8 + quad;
            uint32_t af[2][4], bf[8][2];
#pragma unroll
            for (int mt = 0; mt < 2; mt++) {
                const int m = warpM * 32 + mt * 16 + grp;
                af[mt][0] = f2tf32(sa[(m    ) * PADK + k    ]);
                af[mt][1] = f2tf32(sa[(m + 8) * PADK + k    ]);
                af[mt][2] = f2tf32(sa[(m    ) * PADK + k + 4]);
                af[mt][3] = f2tf32(sa[(m + 8) * PADK + k + 4]);
            }
#pragma unroll
            for (int nt = 0; nt < 8; nt++) {
                const int n = warpN * 64 + nt * 8 + grp;
                bf[nt][0] = f2tf32(sb[n * PADK + k    ]);
                bf[nt][1] = f2tf32(sb[n * PADK + k + 4]);
            }
#pragma unroll
            for (int mt = 0; mt < 2; mt++)
#pragma unroll
                for (int nt = 0; nt < 8; nt++)
                    mma_tf32(acc[mt][nt], af[mt], bf[nt]);
        }
    }

    // epilogue: m16n8 frag -> (row grp, col quad*2), (row grp+8, ...)
#pragma unroll
    for (int mt = 0; mt < 2; mt++) {
        const int m = bm + warpM * 32 + mt * 16 + grp;
#pragma unroll
        for (int nt = 0; nt < 8; nt++) {
            const int n = bn + warpN * 64 + nt * 8 + quad * 2;
            float b0 = bias[n], b1 = bias[n + 1];
            float2 v0 = make_float2(acc[mt][nt][0] + b0, acc[mt][nt][1] + b1);
            float2 v1 = make_float2(acc[mt][nt][2] + b0, acc[mt][nt][3] + b1);
            if (relu) {
                v0.x = fmaxf(v0.x, 0.f); v0.y = fmaxf(v0.y, 0.f);
                v1.x = fmaxf(v1.x, 0.f); v1.y = fmaxf(v1.y, 0.f);
            }
            *(float2*)&C[(size_t)m * ldc + n]       = v0;
            *(float2*)&C[(size_t)(m + 8) * ldc + n] = v1;
        }
    }
}

// ---------------------------------------------------------------------------
// Tiled transpose: src [z][R][C] -> dst [z][C][R]
// ---------------------------------------------------------------------------
__global__ void transpose_rk(const float* __restrict__ src, float* __restrict__ dst,
                             int R, int C)
{
    __shared__ float t[32][33];
    const size_t zo = (size_t)blockIdx.z * R * C;
    const int c0 = blockIdx.x * 32, r0 = blockIdx.y * 32;
    const int tx = threadIdx.x, ty = threadIdx.y;
#pragma unroll
    for (int j = 0; j < 32; j += 8)
        t[ty + j][tx] = src[zo + (size_t)(r0 + ty + j) * C + c0 + tx];
    __syncthreads();
#pragma unroll
    for (int j = 0; j < 32; j += 8)
        dst[zo + (size_t)(c0 + ty + j) * R + r0 + tx] = t[tx][ty + j];
}

// ---------------------------------------------------------------------------
// Register causal softmax: 256 threads/row, 4 elems/thread (float4).
// Invalid (masked) columns write 0 -> also provides diag-tile zero-fill.
// ---------------------------------------------------------------------------
__global__ void __launch_bounds__(256) softmax_causal()
{
    const int l = blockIdx.x;
    const int i = blockIdx.y;
    float* row = g_logits + ((size_t)i * LL + l) * LL;
    const int n = l + 1;                          // valid columns
    const int diagEnd = ((l >> 7) + 1) << 7;      // written region

    const int t = threadIdx.x;
    const int c = t * 4;
    const bool inRange = (c < diagEnd);

    __shared__ float red[8];
    const int wid = t >> 5, lane = t & 31;

    float4 v = make_float4(0.f, 0.f, 0.f, 0.f);
    if (inRange) v = *(const float4*)&row[c];

    bool m0 = (c + 0) < n, m1 = (c + 1) < n, m2 = (c + 2) < n, m3 = (c + 3) < n;

    float vmax = -1e30f;
    if (m0) vmax = v.x;
    if (m1) vmax = fmaxf(vmax, v.y);
    if (m2) vmax = fmaxf(vmax, v.z);
    if (m3) vmax = fmaxf(vmax, v.w);
#pragma unroll
    for (int o = 16; o; o >>= 1) vmax = fmaxf(vmax, __shfl_xor_sync(0xFFFFFFFF, vmax, o));
    if (lane == 0) red[wid] = vmax;
    __syncthreads();
    vmax = red[0];
#pragma unroll
    for (int j = 1; j < 8; j++) vmax = fmaxf(vmax, red[j]);
    __syncthreads();

    float e0 = m0 ? __expf(v.x - vmax) : 0.f;
    float e1 = m1 ? __expf(v.y - vmax) : 0.f;
    float e2 = m2 ? __expf(v.z - vmax) : 0.f;
    float e3 = m3 ? __expf(v.w - vmax) : 0.f;
    float s = e0 + e1 + e2 + e3;
#pragma unroll
    for (int o = 16; o; o >>= 1) s += __shfl_xor_sync(0xFFFFFFFF, s, o);
    if (lane == 0) red[wid] = s;
    __syncthreads();
    s = red[0];
#pragma unroll
    for (int j = 1; j < 8; j++) s += red[j];
    const float inv = 1.0f / s;

    if (inRange) {
        float4 o = make_float4(e0 * inv, e1 * inv, e2 * inv, e3 * inv);
        *(float4*)&row[c] = o;
    }
}

// ---------------------------------------------------------------------------
// PV: out[i] = probs[i] @ v[i] -> concat layout (SIMT; memory-bound)
// v[i][m][d] = proj[m*4+bv][1024 + kv*64 + d], bv = i/16, kv = i%16.
// ---------------------------------------------------------------------------
__global__ void __launch_bounds__(256) gemm_pv()
{
    const int i  = blockIdx.y;
    const int bt = blockIdx.x;
    const int bv = i >> 4, kv = i & 15;
    const float* P = g_logits + (size_t)i * LL * LL;
    const float* V = g_proj + (size_t)bv * PD + DD + kv * DHH;

    __shared__ __align__(16) float Ps[16][128];
    __shared__ __align__(16) float Vs[16][64];
    const int tid = threadIdx.x;
    const int lr  = tid >> 2;
    const int lc4 = (tid & 3) * 4;
    const int vr  = tid >> 4;
    const int vc4 = (tid & 15) * 4;
    const int ty  = tid >> 4, tx = tid & 15;
    const int bm  = bt * 128;
    const int kEnd = bm + 128;

    float acc[8][4] = {};

    for (int k0 = 0; k0 < kEnd; k0 += 16) {
#pragma unroll
        for (int rr = 0; rr < 2; rr++) {
            int r = lr + rr * 64;
            float4 a = *(const float4*)&P[(size_t)(bm + r) * LL + k0 + lc4];
            Ps[lc4+0][r] = a.x; Ps[lc4+1][r] = a.y; Ps[lc4+2][r] = a.z; Ps[lc4+3][r] = a.w;
        }
        {
            float4 b = *(const float4*)&V[(size_t)(k0 + vr) * (size_t)(BSZ * PD) + vc4];
            *(float4*)&Vs[vr][vc4] = b;
        }
        __syncthreads();
#pragma unroll
        for (int kk = 0; kk < 16; kk++) {
            float ra[8], rb[4];
#pragma unroll
            for (int ii = 0; ii < 8; ii++) ra[ii] = Ps[kk][ty*8+ii];
#pragma unroll
            for (int jj = 0; jj < 4; jj++) rb[jj] = Vs[kk][tx*4+jj];
#pragma unroll
            for (int ii = 0; ii < 8; ii++)
#pragma unroll
                for (int jj = 0; jj < 4; jj++)
                    acc[ii][jj] = fmaf(ra[ii], rb[jj], acc[ii][jj]);
        }
        __syncthreads();
    }
#pragma unroll
    for (int ii = 0; ii < 8; ii++) {
        int l = bm + ty*8 + ii;
        float* dst = g_outcat + ((size_t)l * 4 + bv) * DD + kv * DHH + tx * 4;
#pragma unroll
        for (int jj = 0; jj < 4; jj++) dst[jj] = acc[ii][jj];
    }
}

// ---------------------------------------------------------------------------
extern "C" void kernel_launch(void* const* d_in, const int* in_sizes, int n_in,
                              void* d_out, int out_size)
{
    (void)in_sizes; (void)n_in; (void)out_size;
    const float* x  = (const float*)d_in[0];
    // d_in[1] = attention_mask (exactly causal; implemented structurally)
    const float* Wi = (const float*)d_in[2];
    const float* bi = (const float*)d_in[3];
    const float* w1 = (const float*)d_in[4];
    const float* b1 = (const float*)d_in[5];
    const float* w2 = (const float*)d_in[6];
    const float* b2 = (const float*)d_in[7];
    const float* Wo = (const float*)d_in[8];
    const float* bo = (const float*)d_in[9];
    float* out = (float*)d_out;

    float *proj, *hid, *logits, *outcat, *w1t, *w2t;
    cudaGetSymbolAddress((void**)&proj,   g_proj);
    cudaGetSymbolAddress((void**)&hid,    g_hid);
    cudaGetSymbolAddress((void**)&logits, g_logits);
    cudaGetSymbolAddress((void**)&outcat, g_outcat);
    cudaGetSymbolAddress((void**)&w1t,    g_w1t);
    cudaGetSymbolAddress((void**)&w2t,    g_w2t);

    cudaFuncSetAttribute(gemm_mma, cudaFuncAttributeMaxDynamicSharedMemorySize, SMEM_BYTES);

    // weight transposes to K-major (w1: [h][64][1024] -> [h][1024][64]; w2 likewise)
    transpose_rk<<<dim3(32, 2, NHH),  dim3(32, 8)>>>(w1, w1t, DHH, LL);
    transpose_rk<<<dim3(32, 32, NHH), dim3(32, 8)>>>(w2, w2t, LL, LL);

    // K1: proj = x @ Wi^T + bi                 (4096 x 2048 x 1024)
    gemm_mma<<<dim3(PD/128, RR/128), 256, SMEM_BYTES>>>(0, DD, 0, x, Wi, bi, proj);
    // K2: hid = relu(q @ w1 + b1)              (16 x [4096 x 1024 x 64])
    gemm_mma<<<dim3(LL/128, RR/128, NHH), 256, SMEM_BYTES>>>(1, DHH, 1, proj, w1t, b1, hid);
    // K3: logits (lower-tri tiles) + b2        (64 x tri[1024 x 1024 x 1024])
    gemm_mma<<<dim3(LL/128, LL/128, NB), 256, SMEM_BYTES>>>(2, LL, 0, hid, w2t, b2, logits);
    // K4: causal softmax in place
    softmax_causal<<<dim3(LL, NB), 256>>>();
    // K5: out = probs @ v -> concat layout
    gemm_pv<<<dim3(LL/128, NB), 256>>>();
    // K6: y = outcat @ Wo^T + bo               (4096 x 1024 x 1024)
    gemm_mma<<<dim3(DD/128, RR/128), 256, SMEM_BYTES>>>(3, DD, 0, outcat, Wo, bo, out);
}

// round 5
// speedup vs baseline: 3.6042x; 1.3202x over previous
#include <cuda_runtime.h>
#include <cstdint>
#include <math.h>

// Shapes (fixed by the problem)
#define LL   1024
#define BSZ  4
#define DD   1024
#define NHH  16
#define DHH  64
#define PD   2048          // 2*D
#define RR   4096          // L*BS
#define NB   64            // BS*NH batch count for attention

// Scratch (device globals: allocation-free kernel_launch)
__device__ float g_proj[(size_t)RR * PD];            // 32 MB (tf32-rounded)
__device__ float g_hid [(size_t)NHH * RR * LL];      // 268 MB (tf32-rounded)
__device__ float g_logits[(size_t)NB * LL * LL];     // 268 MB (raw; probs rounded)
__device__ float g_outcat[(size_t)RR * DD];          // 17 MB (tf32-rounded)
__device__ float g_w1t[(size_t)NHH * LL * DHH];      // 4 MB  (rounded)
__device__ float g_w2t[(size_t)NHH * LL * LL];       // 64 MB (rounded)
__device__ float g_xr [(size_t)RR * DD];             // 16 MB (x rounded)
__device__ float g_wir[(size_t)PD * DD];             // 8 MB  (Wi rounded)
__device__ float g_wor[(size_t)DD * DD];             // 4 MB  (Wo rounded)
__device__ float g_vt [(size_t)BSZ * LL * LL];       // 16 MB (V^T per batch, rounded)

// ---------------------------------------------------------------------------
__device__ __forceinline__ uint32_t f2tf32(float f) {
    uint32_t u;
    asm("cvt.rna.tf32.f32 %0, %1;" : "=r"(u) : "f"(f));
    return u;
}
__device__ __forceinline__ float rndf(float f) { return __uint_as_float(f2tf32(f)); }

__device__ __forceinline__ uint32_t smem_u32(const void* p) {
    uint32_t a;
    asm("{ .reg .u64 t; cvta.to.shared.u64 t, %1; cvt.u32.u64 %0, t; }" : "=r"(a) : "l"(p));
    return a;
}
__device__ __forceinline__ void cp_async16(uint32_t dst, const void* src) {
    asm volatile("cp.async.cg.shared.global [%0], [%1], 16;" :: "r"(dst), "l"(src));
}
__device__ __forceinline__ void cp_commit() {
    asm volatile("cp.async.commit_group;" ::: "memory");
}
__device__ __forceinline__ void cp_wait1() {
    asm volatile("cp.async.wait_group 1;" ::: "memory");
}
__device__ __forceinline__ void ldsm4(uint32_t& r0, uint32_t& r1, uint32_t& r2, uint32_t& r3,
                                      uint32_t addr) {
    asm volatile("ldmatrix.sync.aligned.m8n8.x4.shared.b16 {%0,%1,%2,%3}, [%4];"
                 : "=r"(r0), "=r"(r1), "=r"(r2), "=r"(r3) : "r"(addr));
}
__device__ __forceinline__ void mma_tf32(float c[4], const uint32_t a[4], const uint32_t b[2]) {
    asm volatile(
        "mma.sync.aligned.m16n8k8.row.col.f32.tf32.tf32.f32 "
        "{%0,%1,%2,%3}, {%4,%5,%6,%7}, {%8,%9}, {%0,%1,%2,%3};"
        : "+f"(c[0]), "+f"(c[1]), "+f"(c[2]), "+f"(c[3])
        : "r"(a[0]), "r"(a[1]), "r"(a[2]), "r"(a[3]), "r"(b[0]), "r"(b[1]));
}

// ---------------------------------------------------------------------------
// Tensor-core tf32 GEMM: C = act(A @ B^T + bias). Inputs pre-rounded to tf32.
// Block tile 128x128, K-chunk 32, 3-stage cp.async, ldmatrix fragment loads,
// fragment double-buffering. 8 warps (4M x 2N), warp tile 32x64.
// mode: 0=proj  1=hid(relu)  2=logits(tri)  3=out
// Epilogue rounds output to tf32 for modes 0,1 (they feed later mmas).
// ---------------------------------------------------------------------------
#define PADK 36
#define STAGE_F (128 * PADK)
#define SMEM_BYTES (2 * 3 * STAGE_F * 4)     // 110592
#define TS (16 * PADK * 4)                   // 16-row tile stride in bytes

__global__ void __launch_bounds__(256, 2) gemm_mma(
    int mode, int K, int relu,
    const float* __restrict__ Ain, const float* __restrict__ Bin,
    const float* __restrict__ biasIn, float* __restrict__ Cout)
{
    const int bm = blockIdx.y * 128;
    const int bn = blockIdx.x * 128;

    const float* A; const float* B; const float* bias; float* C;
    size_t sA, sB, ldc;
    if (mode == 0) {            // proj = x @ Wi^T + bi
        A = Ain; sA = DD; B = Bin; sB = DD; bias = biasIn; C = Cout; ldc = PD;
    } else if (mode == 1) {     // hid[h] = relu(proj[:, h*64:] @ w1t[h]^T + b1[h])
        int h = blockIdx.z;
        A = Ain + h * DHH;                sA = PD;
        B = Bin + (size_t)h * LL * DHH;   sB = DHH;
        bias = biasIn + h * LL;
        C = Cout + (size_t)h * RR * LL;   ldc = LL;
    } else if (mode == 2) {     // logits[i] = hid_rows(bq) @ w2t[kq]^T + b2[kq]
        if (blockIdx.x > blockIdx.y) return;    // causal: lower-tri tiles only
        int i = blockIdx.z, kq = i >> 2, bq = i & 3;
        A = Ain + (size_t)kq * RR * LL + bq * LL; sA = 4 * LL;
        B = Bin + (size_t)kq * LL * LL;           sB = LL;
        bias = biasIn + kq * LL;
        C = Cout + (size_t)i * LL * LL;           ldc = LL;
    } else {                    // out = outcat @ Wo^T + bo
        A = Ain; sA = DD; B = Bin; sB = DD; bias = biasIn; C = Cout; ldc = DD;
    }

    extern __shared__ __align__(16) float smem[];
    float* As = smem;                    // [3][128][PADK]
    float* Bs = smem + 3 * STAGE_F;      // [3][128][PADK]

    const int tid   = threadIdx.x;
    const int wid   = tid >> 5, lane = tid & 31;
    const int warpM = wid & 3;
    const int warpN = wid >> 2;
    const int grp   = lane >> 2;
    const int quad  = lane & 3;

    const int T = K / 32;

    const uint32_t sA0 = smem_u32(As);
    const uint32_t sB0 = smem_u32(Bs);
    // ldmatrix per-lane row offsets (bytes)
    const uint32_t aRow = (uint32_t)(((warpM * 32 + (lane & 15)) * PADK + (lane >> 4) * 4) * 4);
    const uint32_t bRow = (uint32_t)(((warpN * 64 + ((lane >> 4) & 1) * 8 + (lane & 7)) * PADK
                                      + ((lane >> 3) & 1) * 4) * 4);

    auto issue = [&](int chunk, int buf) {
        const int k0 = chunk * 32;
        float* sa = As + buf * STAGE_F;
        float* sb = Bs + buf * STAGE_F;
#pragma unroll
        for (int j = 0; j < 4; j++) {
            const int idx = tid + j * 256;
            const int r = idx >> 3, c4 = (idx & 7) * 4;
            cp_async16(smem_u32(&sa[r * PADK + c4]),
                       &A[(size_t)(bm + r) * sA + k0 + c4]);
            cp_async16(smem_u32(&sb[r * PADK + c4]),
                       &B[(size_t)(bn + r) * sB + k0 + c4]);
        }
    };

    issue(0, 0); cp_commit();
    if (1 < T) issue(1, 1);
    cp_commit();

    float acc[2][8][4] = {};
    uint32_t af[2][2][4], bf[2][8][2];

#pragma unroll 1
    for (int t = 0; t < T; t++) {
        cp_wait1();
        __syncthreads();

        if (t + 2 < T) issue(t + 2, (t + 2) % 3);
        cp_commit();

        const uint32_t aSt = sA0 + (uint32_t)((t % 3) * STAGE_F * 4);
        const uint32_t bSt = sB0 + (uint32_t)((t % 3) * STAGE_F * 4);

        // load fragments for ks=0
#pragma unroll
        for (int mt = 0; mt < 2; mt++)
            ldsm4(af[0][mt][0], af[0][mt][1], af[0][mt][2], af[0][mt][3],
                  aSt + aRow + mt * TS);
#pragma unroll
        for (int p = 0; p < 4; p++)
            ldsm4(bf[0][2*p][0], bf[0][2*p][1], bf[0][2*p+1][0], bf[0][2*p+1][1],
                  bSt + bRow + p * TS);

#pragma unroll
        for (int ks = 0; ks < 4; ks++) {
            const int cur = ks & 1, nxt = cur ^ 1;
            if (ks < 3) {
                const uint32_t ko = (uint32_t)((ks + 1) * 32);
#pragma unroll
                for (int mt = 0; mt < 2; mt++)
                    ldsm4(af[nxt][mt][0], af[nxt][mt][1], af[nxt][mt][2], af[nxt][mt][3],
                          aSt + aRow + mt * TS + ko);
#pragma unroll
                for (int p = 0; p < 4; p++)
                    ldsm4(bf[nxt][2*p][0], bf[nxt][2*p][1], bf[nxt][2*p+1][0], bf[nxt][2*p+1][1],
                          bSt + bRow + p * TS + ko);
            }
#pragma unroll
            for (int mt = 0; mt < 2; mt++)
#pragma unroll
                for (int nt = 0; nt < 8; nt++)
                    mma_tf32(acc[mt][nt], af[cur][mt], bf[cur][nt]);
        }
    }

    const bool rnd_out = (mode < 2);
#pragma unroll
    for (int mt = 0; mt < 2; mt++) {
        const int m = bm + warpM * 32 + mt * 16 + grp;
#pragma unroll
        for (int nt = 0; nt < 8; nt++) {
            const int n = bn + warpN * 64 + nt * 8 + quad * 2;
            float b0 = bias[n], b1 = bias[n + 1];
            float2 v0 = make_float2(acc[mt][nt][0] + b0, acc[mt][nt][1] + b1);
            float2 v1 = make_float2(acc[mt][nt][2] + b0, acc[mt][nt][3] + b1);
            if (relu) {
                v0.x = fmaxf(v0.x, 0.f); v0.y = fmaxf(v0.y, 0.f);
                v1.x = fmaxf(v1.x, 0.f); v1.y = fmaxf(v1.y, 0.f);
            }
            if (rnd_out) {
                v0.x = rndf(v0.x); v0.y = rndf(v0.y);
                v1.x = rndf(v1.x); v1.y = rndf(v1.y);
            }
            *(float2*)&C[(size_t)m * ldc + n]       = v0;
            *(float2*)&C[(size_t)(m + 8) * ldc + n] = v1;
        }
    }
}

// ---------------------------------------------------------------------------
// PV with tf32 mma: out[i] = probs[i] @ V[i], V pre-transposed K-major in g_vt.
// Block tile 128x64 (M=l-rows, N=DH), K-chunk 32, 3-stage cp.async, ldmatrix.
// 8 warps, warp tile 16x64. Writes concat layout (rounded: A operand of K6).
// ---------------------------------------------------------------------------
#define PV_AF (128 * PADK)
#define PV_BF (64 * PADK)
#define PV_STAGE (PV_AF + PV_BF)
#define PV_SMEM (3 * PV_STAGE * 4)           // 82944

__global__ void __launch_bounds__(256, 2) gemm_pv_mma()
{
    const int i  = blockIdx.y;
    const int ti = blockIdx.x;
    const int bv = i >> 4, kv = i & 15;
    const float* P  = g_logits + (size_t)i * LL * LL;
    const float* Vt = g_vt + (size_t)bv * LL * LL + (size_t)(kv * DHH) * LL; // 64 rows x 1024

    extern __shared__ __align__(16) float smem[];
    float* As = smem;                         // [3][128][PADK]
    float* Bs = smem + 3 * PV_AF;             // [3][64][PADK]

    const int tid = threadIdx.x;
    const int wid = tid >> 5, lane = tid & 31;
    const int grp = lane >> 2, quad = lane & 3;
    const int bm  = ti * 128;
    const int T   = (ti + 1) * 4;             // K = bm+128 over 32-chunks

    const uint32_t sA0 = smem_u32(As);
    const uint32_t sB0 = smem_u32(Bs);
    const uint32_t aRow = (uint32_t)(((wid * 16 + (lane & 15)) * PADK + (lane >> 4) * 4) * 4);
    const uint32_t bRow = (uint32_t)(((((lane >> 4) & 1) * 8 + (lane & 7)) * PADK
                                      + ((lane >> 3) & 1) * 4) * 4);

    auto issue = [&](int chunk, int buf) {
        const int k0 = chunk * 32;
        float* sa = As + buf * PV_AF;
        float* sb = Bs + buf * PV_BF;
#pragma unroll
        for (int j = 0; j < 4; j++) {
            const int idx = tid + j * 256;
            const int r = idx >> 3, c4 = (idx & 7) * 4;
            cp_async16(smem_u32(&sa[r * PADK + c4]),
                       &P[(size_t)(bm + r) * LL + k0 + c4]);
        }
#pragma unroll
        for (int j = 0; j < 2; j++) {
            const int idx = tid + j * 256;
            const int r = idx >> 3, c4 = (idx & 7) * 4;
            cp_async16(smem_u32(&sb[r * PADK + c4]),
                       &Vt[(size_t)r * LL + k0 + c4]);
        }
    };

    issue(0, 0); cp_commit();
    issue(1, 1); cp_commit();

    float acc[8][4] = {};
    uint32_t af[2][4], bf[2][8][2];

#pragma unroll 1
    for (int t = 0; t < T; t++) {
        cp_wait1();
        __syncthreads();

        if (t + 2 < T) issue(t + 2, (t + 2) % 3);
        cp_commit();

        const uint32_t aSt = sA0 + (uint32_t)((t % 3) * PV_AF * 4);
        const uint32_t bSt = sB0 + (uint32_t)((t % 3) * PV_BF * 4);

        ldsm4(af[0][0], af[0][1], af[0][2], af[0][3], aSt + aRow);
#pragma unroll
        for (int p = 0; p < 4; p++)
            ldsm4(bf[0][2*p][0], bf[0][2*p][1], bf[0][2*p+1][0], bf[0][2*p+1][1],
                  bSt + bRow + p * TS);

#pragma unroll
        for (int ks = 0; ks < 4; ks++) {
            const int cur = ks & 1, nxt = cur ^ 1;
            if (ks < 3) {
                const uint32_t ko = (uint32_t)((ks + 1) * 32);
                ldsm4(af[nxt][0], af[nxt][1], af[nxt][2], af[nxt][3], aSt + aRow + ko);
#pragma unroll
                for (int p = 0; p < 4; p++)
                    ldsm4(bf[nxt][2*p][0], bf[nxt][2*p][1], bf[nxt][2*p+1][0], bf[nxt][2*p+1][1],
                          bSt + bRow + p * TS + ko);
            }
#pragma unroll
            for (int nt = 0; nt < 8; nt++)
                mma_tf32(acc[nt], af[cur], bf[cur][nt]);
        }
    }

    // epilogue: rows bm + wid*16 + grp (+8); cols nt*8 + quad*2 (+1); rounded.
    const int l0 = bm + wid * 16 + grp;
#pragma unroll
    for (int nt = 0; nt < 8; nt++) {
        const int d = nt * 8 + quad * 2;
        float* dst0 = g_outcat + ((size_t)l0 * 4 + bv) * DD + kv * DHH + d;
        float* dst1 = g_outcat + ((size_t)(l0 + 8) * 4 + bv) * DD + kv * DHH + d;
        dst0[0] = rndf(acc[nt][0]); dst0[1] = rndf(acc[nt][1]);
        dst1[0] = rndf(acc[nt][2]); dst1[1] = rndf(acc[nt][3]);
    }
}

// ---------------------------------------------------------------------------
// Prep kernels
// ---------------------------------------------------------------------------
__global__ void round_copy(const float* __restrict__ src, float* __restrict__ dst, int n4)
{
    int i = blockIdx.x * blockDim.x + threadIdx.x;
    if (i < n4) {
        float4 v = ((const float4*)src)[i];
        v.x = rndf(v.x); v.y = rndf(v.y); v.z = rndf(v.z); v.w = rndf(v.w);
        ((float4*)dst)[i] = v;
    }
}

// Tiled transpose with tf32 rounding: src [z][R][C] -> dst [z][C][R]
__global__ void transpose_rk(const float* __restrict__ src, float* __restrict__ dst,
                             int R, int C)
{
    __shared__ float t[32][33];
    const size_t zo = (size_t)blockIdx.z * R * C;
    const int c0 = blockIdx.x * 32, r0 = blockIdx.y * 32;
    const int tx = threadIdx.x, ty = threadIdx.y;
#pragma unroll
    for (int j = 0; j < 32; j += 8)
        t[ty + j][tx] = rndf(src[zo + (size_t)(r0 + ty + j) * C + c0 + tx]);
    __syncthreads();
#pragma unroll
    for (int j = 0; j < 32; j += 8)
        dst[zo + (size_t)(c0 + ty + j) * R + r0 + tx] = t[tx][ty + j];
}

// V transpose: g_vt[bv][dcol][m] = proj[(m*4+bv)*PD + DD + dcol]  (already rounded)
__global__ void transpose_v()
{
    __shared__ float t[32][33];
    const int bv = blockIdx.z;
    const int c0 = blockIdx.x * 32, r0 = blockIdx.y * 32;   // c=dcol, r=m
    const int tx = threadIdx.x, ty = threadIdx.y;
#pragma unroll
    for (int j = 0; j < 32; j += 8)
        t[ty + j][tx] = g_proj[((size_t)(r0 + ty + j) * 4 + bv) * PD + DD + c0 + tx];
    __syncthreads();
#pragma unroll
    for (int j = 0; j < 32; j += 8)
        g_vt[(size_t)bv * LL * LL + (size_t)(c0 + ty + j) * LL + r0 + tx] = t[tx][ty + j];
}

// ---------------------------------------------------------------------------
// Register causal softmax; writes tf32-rounded probs (A operand of PV mma).
// Masked columns write 0 -> provides diag-tile zero-fill for PV K-panels.
// ---------------------------------------------------------------------------
__global__ void __launch_bounds__(256) softmax_causal()
{
    const int l = blockIdx.x;
    const int i = blockIdx.y;
    float* row = g_logits + ((size_t)i * LL + l) * LL;
    const int n = l + 1;
    const int diagEnd = ((l >> 7) + 1) << 7;

    const int t = threadIdx.x;
    const int c = t * 4;
    const bool inRange = (c < diagEnd);

    __shared__ float red[8];
    const int wid = t >> 5, lane = t & 31;

    float4 v = make_float4(0.f, 0.f, 0.f, 0.f);
    if (inRange) v = *(const float4*)&row[c];

    bool m0 = (c + 0) < n, m1 = (c + 1) < n, m2 = (c + 2) < n, m3 = (c + 3) < n;

    float vmax = -1e30f;
    if (m0) vmax = v.x;
    if (m1) vmax = fmaxf(vmax, v.y);
    if (m2) vmax = fmaxf(vmax, v.z);
    if (m3) vmax = fmaxf(vmax, v.w);
#pragma unroll
    for (int o = 16; o; o >>= 1) vmax = fmaxf(vmax, __shfl_xor_sync(0xFFFFFFFF, vmax, o));
    if (lane == 0) red[wid] = vmax;
    __syncthreads();
    vmax = red[0];
#pragma unroll
    for (int j = 1; j < 8; j++) vmax = fmaxf(vmax, red[j]);
    __syncthreads();

    float e0 = m0 ? __expf(v.x - vmax) : 0.f;
    float e1 = m1 ? __expf(v.y - vmax) : 0.f;
    float e2 = m2 ? __expf(v.z - vmax) : 0.f;
    float e3 = m3 ? __expf(v.w - vmax) : 0.f;
    float s = e0 + e1 + e2 + e3;
#pragma unroll
    for (int o = 16; o; o >>= 1) s += __shfl_xor_sync(0xFFFFFFFF, s, o);
    if (lane == 0) red[wid] = s;
    __syncthreads();
    s = red[0];
#pragma unroll
    for (int j = 1; j < 8; j++) s += red[j];
    const float inv = 1.0f / s;

    if (inRange) {
        float4 o = make_float4(rndf(e0 * inv), rndf(e1 * inv), rndf(e2 * inv), rndf(e3 * inv));
        *(float4*)&row[c] = o;
    }
}

// ---------------------------------------------------------------------------
extern "C" void kernel_launch(void* const* d_in, const int* in_sizes, int n_in,
                              void* d_out, int out_size)
{
    (void)in_sizes; (void)n_in; (void)out_size;
    const float* x  = (const float*)d_in[0];
    // d_in[1] = attention_mask (exactly causal; implemented structurally)
    const float* Wi = (const float*)d_in[2];
    const float* bi = (const float*)d_in[3];
    const float* w1 = (const float*)d_in[4];
    const float* b1 = (const float*)d_in[5];
    const float* w2 = (const float*)d_in[6];
    const float* b2 = (const float*)d_in[7];
    const float* Wo = (const float*)d_in[8];
    const float* bo = (const float*)d_in[9];
    float* out = (float*)d_out;

    float *proj, *hid, *logits, *w1t, *w2t, *xr, *wir, *wor, *outcat;
    cudaGetSymbolAddress((void**)&proj,   g_proj);
    cudaGetSymbolAddress((void**)&hid,    g_hid);
    cudaGetSymbolAddress((void**)&logits, g_logits);
    cudaGetSymbolAddress((void**)&w1t,    g_w1t);
    cudaGetSymbolAddress((void**)&w2t,    g_w2t);
    cudaGetSymbolAddress((void**)&xr,     g_xr);
    cudaGetSymbolAddress((void**)&wir,    g_wir);
    cudaGetSymbolAddress((void**)&wor,    g_wor);
    cudaGetSymbolAddress((void**)&outcat, g_outcat);

    cudaFuncSetAttribute(gemm_mma,    cudaFuncAttributeMaxDynamicSharedMemorySize, SMEM_BYTES);
    cudaFuncSetAttribute(gemm_pv_mma, cudaFuncAttributeMaxDynamicSharedMemorySize, PV_SMEM);

    // prep: round external mma inputs to tf32; transpose w1/w2 (rounded)
    round_copy<<<(RR*DD/4 + 255)/256, 256>>>(x,  xr,  RR*DD/4);
    round_copy<<<(PD*DD/4 + 255)/256, 256>>>(Wi, wir, PD*DD/4);
    round_copy<<<(DD*DD/4 + 255)/256, 256>>>(Wo, wor, DD*DD/4);
    transpose_rk<<<dim3(32, 2, NHH),  dim3(32, 8)>>>(w1, w1t, DHH, LL);
    transpose_rk<<<dim3(32, 32, NHH), dim3(32, 8)>>>(w2, w2t, LL, LL);

    // K1: proj = x @ Wi^T + bi                 (4096 x 2048 x 1024)
    gemm_mma<<<dim3(PD/128, RR/128), 256, SMEM_BYTES>>>(0, DD, 0, xr, wir, bi, proj);
    // V^T per batch (from rounded proj)
    transpose_v<<<dim3(32, 32, BSZ), dim3(32, 8)>>>();
    // K2: hid = relu(q @ w1 + b1)              (16 x [4096 x 1024 x 64])
    gemm_mma<<<dim3(LL/128, RR/128, NHH), 256, SMEM_BYTES>>>(1, DHH, 1, proj, w1t, b1, hid);
    // K3: logits (lower-tri tiles) + b2        (64 x tri[1024 x 1024 x 1024])
    gemm_mma<<<dim3(LL/128, LL/128, NB), 256, SMEM_BYTES>>>(2, LL, 0, hid, w2t, b2, logits);
    // K4: causal softmax in place (writes rounded probs)
    softmax_causal<<<dim3(LL, NB), 256>>>();
    // K5: out = probs @ v -> concat layout (tf32 mma)
    gemm_pv_mma<<<dim3(LL/128, NB), 256, PV_SMEM>>>();
    // K6: y = outcat @ Wo^T + bo               (4096 x 1024 x 1024)
    gemm_mma<<<dim3(DD/128, RR/128), 256, SMEM_BYTES>>>(3, DD, 0, outcat, wor, bo, out);
}